// round 15
// baseline (speedup 1.0000x reference)
#include <cuda_runtime.h>
#include <stdint.h>
#include <math.h>

#define BB 2
#define NN 5000
#define CC 128
#define EE 65536
#define TT 4
#define ETB (TT*BB)   /* 8 */

typedef unsigned long long ull;

// ---------------- scratch (static device globals; no allocation) ------------
__device__ float d_XN[BB*2*NN*CC];
__device__ float d_Y1[ETB*NN*CC];
__device__ float d_Y2[ETB*NN*CC];
__device__ float d_AGGR[ETB*NN*CC];
__device__ float d_OUTE[ETB*NN*CC];
__device__ float d_ASRC[ETB*NN];
__device__ float d_ADST[ETB*NN];
__device__ float d_U[TT*CC];
__device__ float d_V[TT*CC];
__device__ int   d_CNT[ETB*NN];
__device__ int   d_FILL[ETB*NN];
__device__ int   d_ROWP[ETB*(NN+1)];
__device__ int   d_ESRC[ETB*EE];
__device__ float d_EALPHA[ETB*EE];
__device__ float d_EWS[ETB*EE];
__device__ float d_COLSUM[BB*2*2*CC];
__device__ float d_ATTN[BB*2*2];

__device__ __forceinline__ int et_src(int et){ return et & 1; }
__device__ __forceinline__ int et_dst(int et){ return (et & 1) ^ (et >> 1); }

__device__ __forceinline__ float warpMax(float v){
    #pragma unroll
    for (int o = 16; o > 0; o >>= 1) v = fmaxf(v, __shfl_xor_sync(0xffffffffu, v, o));
    return v;
}
__device__ __forceinline__ float warpSum(float v){
    #pragma unroll
    for (int o = 16; o > 0; o >>= 1) v += __shfl_xor_sync(0xffffffffu, v, o);
    return v;
}

// ---- packed fp32x2 helpers (Blackwell FFMA2) — stage 0 only -----------------
__device__ __forceinline__ ull pack2(float x, float y){
    ull r; asm("mov.b64 %0, {%1, %2};" : "=l"(r) : "f"(x), "f"(y)); return r;
}
__device__ __forceinline__ ull dup2(float x){
    ull r; asm("mov.b64 %0, {%1, %1};" : "=l"(r) : "f"(x)); return r;
}
__device__ __forceinline__ void fma2(ull &d, ull a, ull b){
    asm("fma.rn.f32x2 %0, %1, %2, %0;" : "+l"(d) : "l"(a), "l"(b));
}
__device__ __forceinline__ float2 unpack2(ull v){
    float2 r; asm("mov.b64 {%0, %1}, %2;" : "=f"(r.x), "=f"(r.y) : "l"(v)); return r;
}

// ---- tf32 warp MMA ----------------------------------------------------------
__device__ __forceinline__ void mma_tf32(float* d, const unsigned* a, const unsigned* b){
    asm volatile(
        "mma.sync.aligned.m16n8k8.row.col.f32.tf32.tf32.f32 "
        "{%0,%1,%2,%3}, {%4,%5,%6,%7}, {%8,%9}, {%0,%1,%2,%3};"
        : "+f"(d[0]), "+f"(d[1]), "+f"(d[2]), "+f"(d[3])
        : "r"(a[0]), "r"(a[1]), "r"(a[2]), "r"(a[3]), "r"(b[0]), "r"(b[1]));
}

// ---- cp.async helpers -------------------------------------------------------
__device__ __forceinline__ void cpa16(void* sdst, const void* gsrc, bool ok){
    unsigned int sa = (unsigned int)__cvta_generic_to_shared(sdst);
    int sz = ok ? 16 : 0;
    asm volatile("cp.async.cg.shared.global [%0], [%1], 16, %2;" :: "r"(sa), "l"(gsrc), "r"(sz));
}
#define CPA_COMMIT() asm volatile("cp.async.commit_group;")
#define CPA_WAIT2()  asm volatile("cp.async.wait_group 2;" ::: "memory")

// ---------------- misc small kernels ----------------------------------------
__global__ void zero_kernel(){
    int i = blockIdx.x * blockDim.x + threadIdx.x;
    if (i < ETB*NN){ d_CNT[i] = 0; d_FILL[i] = 0; }
    if (i < BB*2*2*CC) d_COLSUM[i] = 0.f;
}

__global__ void uv_kernel(const float* __restrict__ eproj_w, const float* __restrict__ eproj_b,
                          const float* __restrict__ att_w,   const float* __restrict__ att_b){
    int et = blockIdx.x;
    int cp = threadIdx.x;
    const float* W3 = att_w + (size_t)et*3*CC*CC + 2*CC*CC;
    float u = 0.f, v = 0.f;
    #pragma unroll 4
    for (int c = 0; c < CC; c++){
        float wv = W3[c*CC + cp];
        u = fmaf(eproj_w[et*CC + c], wv, u);
        v = fmaf(eproj_b[et*CC + c], wv, v);
    }
    v += att_b[et*CC + cp];
    d_U[et*CC + cp] = u;
    d_V[et*CC + cp] = v;
}

__global__ void asrc_kernel(const float* __restrict__ lin_src, const float* __restrict__ lin_dst){
    int g = blockIdx.x * 8 + (threadIdx.x >> 5);
    int lane = threadIdx.x & 31;
    if (g >= ETB*NN) return;
    int etb = g / NN, n = g % NN;
    int et = etb >> 1, b = etb & 1;
    int st = et_src(et), dt = et_dst(et);
    const float* xs = d_XN + ((size_t)(b*2 + st)*NN + n)*CC;
    const float* xd = d_XN + ((size_t)(b*2 + dt)*NN + n)*CC;
    float s1 = 0.f, s2 = 0.f;
    #pragma unroll
    for (int c = lane; c < CC; c += 32){
        s1 = fmaf(xs[c], lin_src[et*CC + c], s1);
        s2 = fmaf(xd[c], lin_dst[et*CC + c], s2);
    }
    s1 = warpSum(s1); s2 = warpSum(s2);
    if (lane == 0){
        d_ASRC[etb*NN + n] = s1;
        d_ADST[etb*NN + n] = s2;
    }
}

__global__ void hist_kernel(const int* __restrict__ eidx){
    int idx = blockIdx.x * 256 + threadIdx.x;
    int etb = idx >> 16;
    int e   = idx & (EE - 1);
    int dst = eidx[(etb*2 + 1)*EE + e];
    atomicAdd(&d_CNT[etb*NN + dst], 1);
}

__global__ void scan_kernel(){
    int etb = blockIdx.x;
    int tid = threadIdx.x;                      // 1024 threads
    __shared__ int sh[1024];
    int base = etb * NN;
    int vals[5];
    int tot = 0;
    int start = tid * 5;
    #pragma unroll
    for (int k = 0; k < 5; k++){
        int idx = start + k;
        int c = (idx < NN) ? d_CNT[base + idx] : 0;
        vals[k] = tot;
        tot += c;
    }
    sh[tid] = tot;
    __syncthreads();
    for (int off = 1; off < 1024; off <<= 1){
        int v = (tid >= off) ? sh[tid - off] : 0;
        __syncthreads();
        sh[tid] += v;
        __syncthreads();
    }
    int offset = sh[tid] - tot;
    int rbase = etb * (NN + 1);
    #pragma unroll
    for (int k = 0; k < 5; k++){
        int idx = start + k;
        if (idx < NN) d_ROWP[rbase + idx] = offset + vals[k];
    }
    if (tid == 0) d_ROWP[rbase + NN] = EE;
}

__global__ void scatter_kernel(const int* __restrict__ eidx, const float* __restrict__ ew){
    int idx = blockIdx.x * 256 + threadIdx.x;
    int etb = idx >> 16;
    int e   = idx & (EE - 1);
    int src = eidx[(etb*2 + 0)*EE + e];
    int dst = eidx[(etb*2 + 1)*EE + e];
    int pos = d_ROWP[etb*(NN+1) + dst] + atomicAdd(&d_FILL[etb*NN + dst], 1);
    float a = d_ASRC[etb*NN + src] + d_ADST[etb*NN + dst];
    a = (a > 0.f) ? a : 0.2f * a;
    int o = etb*EE + pos;
    d_ESRC[o]   = src;
    d_EALPHA[o] = a;
    d_EWS[o]    = ew[etb*EE + e];
}

// ---------------- STAGE 0 GEMM (fp32 FFMA2, exact — feeds softmax logits) ----
__global__ void __launch_bounds__(256)
gemm_stage0(const float* __restrict__ x,
            const float* __restrict__ proj_w, const float* __restrict__ proj_b)
{
    __shared__ __align__(16) float As[2][8][132];
    __shared__ __align__(16) float Ws[2][8][128];

    const int z   = blockIdx.y;
    const int tid = threadIdx.x;
    const int tx  = tid & 15;
    const int ty  = tid >> 4;

    int b = z >> 1, nt = z & 1;
    const float* A0  = x + (size_t)(b*2*NN + nt*NN)*CC;
    const float* W   = proj_w + (size_t)nt*CC*CC;
    const float* bias = proj_b + nt*CC;
    float* OUT = d_XN + (size_t)z*NN*CC;

    ull acc[8][4];
    #pragma unroll
    for (int i = 0; i < 8; i++)
        #pragma unroll
        for (int j = 0; j < 4; j++) acc[i][j] = 0ull;

    const int m0 = blockIdx.x * 128;
    const int ar  = tid >> 1;
    const int ak4 = (tid & 1) * 4;
    const int wk  = tid >> 5;
    const int wn  = (tid & 31) * 4;
    const int am  = m0 + ar;
    const bool aok = (am < NN);

    float4 aReg = make_float4(0.f,0.f,0.f,0.f);
    if (aok) aReg = *(const float4*)(A0 + (size_t)am*CC + ak4);
    float4 wReg = *(const float4*)(W + (size_t)wk*CC + wn);

    As[0][ak4+0][ar] = aReg.x;
    As[0][ak4+1][ar] = aReg.y;
    As[0][ak4+2][ar] = aReg.z;
    As[0][ak4+3][ar] = aReg.w;
    *(float4*)&Ws[0][wk][wn] = wReg;
    __syncthreads();

    for (int kc = 0; kc < 128; kc += 8){
        const int buf = (kc >> 3) & 1;
        const int kn  = kc + 8;
        const bool more = (kn < 128);

        if (more){
            aReg = make_float4(0.f,0.f,0.f,0.f);
            if (aok) aReg = *(const float4*)(A0 + (size_t)am*CC + kn + ak4);
            wReg = *(const float4*)(W + (size_t)(kn + wk)*CC + wn);
        }

        #pragma unroll
        for (int kk = 0; kk < 8; kk++){
            float4 bl = *(float4*)&Ws[buf][kk][tx*4];
            float4 bh = *(float4*)&Ws[buf][kk][64 + tx*4];
            ull bp0 = pack2(bl.x, bl.y);
            ull bp1 = pack2(bl.z, bl.w);
            ull bp2 = pack2(bh.x, bh.y);
            ull bp3 = pack2(bh.z, bh.w);
            float4 a0 = *(float4*)&As[buf][kk][ty*8];
            float4 a1 = *(float4*)&As[buf][kk][ty*8 + 4];
            float av[8] = {a0.x, a0.y, a0.z, a0.w, a1.x, a1.y, a1.z, a1.w};
            #pragma unroll
            for (int i = 0; i < 8; i++){
                ull ad = dup2(av[i]);
                fma2(acc[i][0], ad, bp0);
                fma2(acc[i][1], ad, bp1);
                fma2(acc[i][2], ad, bp2);
                fma2(acc[i][3], ad, bp3);
            }
        }

        if (more){
            const int nb = buf ^ 1;
            As[nb][ak4+0][ar] = aReg.x;
            As[nb][ak4+1][ar] = aReg.y;
            As[nb][ak4+2][ar] = aReg.z;
            As[nb][ak4+3][ar] = aReg.w;
            *(float4*)&Ws[nb][wk][wn] = wReg;
        }
        __syncthreads();
    }

    const int c0 = tx*4;
    const int c1 = 64 + tx*4;
    #pragma unroll
    for (int i = 0; i < 8; i++){
        int m = m0 + ty*8 + i;
        if (m < NN){
            float2 v0 = unpack2(acc[i][0]);
            float2 v1 = unpack2(acc[i][1]);
            float2 v2 = unpack2(acc[i][2]);
            float2 v3 = unpack2(acc[i][3]);
            v0.x += bias[c0];   v0.y += bias[c0+1];
            v1.x += bias[c0+2]; v1.y += bias[c0+3];
            v2.x += bias[c1];   v2.y += bias[c1+1];
            v3.x += bias[c1+2]; v3.y += bias[c1+3];
            float* dst = OUT + (size_t)m*CC;
            *(float4*)(dst + c0) = make_float4(v0.x, v0.y, v1.x, v1.y);
            *(float4*)(dst + c1) = make_float4(v2.x, v2.y, v3.x, v3.y);
        }
    }
}

// ---------------- STAGES 1/2/3 GEMM: tf32 mma.sync, 4-stage cp.async ---------
// CTA tile 128x64 (n split across grid.y), 8 warps, warp tile 32x32 -> 32 acc
// regs -> 3 CTAs/SM (24 warps). A smem m-major stride 12; W smem k-major
// stride 72 (8c+r bank permutation, conflict-free).
template<int STAGE>
__global__ void __launch_bounds__(256, 3)
gemm_mma(const float* __restrict__ att_w,
         const float* __restrict__ agg_w,  const float* __restrict__ agg_b,
         const float* __restrict__ klin_w, const float* __restrict__ klin_b)
{
    constexpr int KTOT = (STAGE == 2) ? 256 : 128;
    constexpr int NCH  = KTOT / 8;
    __shared__ __align__(16) float As[4][128][12];
    __shared__ __align__(16) float Ws[4][8][72];
    __shared__ float cs[64];

    const int z2   = blockIdx.y;
    const int nbase = (z2 & 1) * 64;      // n-half of the 128-wide output
    const int z    = z2 >> 1;
    const int tid  = threadIdx.x;
    const int wid  = tid >> 5;
    const int lane = tid & 31;
    const int wm   = (wid & 3) * 32;      // 4 m-groups
    const int wnq  = (wid >> 2) * 32;     // 2 n-groups (local)
    const int r    = lane >> 2;
    const int c    = lane & 3;

    const float* A0 = nullptr; const float* A1 = nullptr;
    const float* W  = nullptr; const float* bias = nullptr;
    float* OUT = nullptr; float* colsum = nullptr;

    if (STAGE == 1){
        int etb = z >> 1, which = z & 1;
        int et = etb >> 1, b = etb & 1;
        int nt = which ? et_dst(et) : et_src(et);
        A0  = d_XN + (size_t)(b*2 + nt)*NN*CC;
        W   = att_w + (size_t)et*3*CC*CC + (size_t)which*CC*CC + nbase;
        OUT = (which ? d_Y2 : d_Y1) + (size_t)etb*NN*CC;
    } else if (STAGE == 2){
        int etb = z; int et = etb >> 1, b = etb & 1;
        int dt = et_dst(et);
        A0  = d_AGGR + (size_t)etb*NN*CC;
        A1  = d_XN + (size_t)(b*2 + dt)*NN*CC;
        W   = agg_w + (size_t)et*2*CC*CC + nbase;
        bias = agg_b + et*CC;
        OUT = d_OUTE + (size_t)etb*NN*CC;
    } else {
        int etb = z; int et = etb >> 1, b = etb & 1;
        int dt = et_dst(et);
        A0  = d_OUTE + (size_t)etb*NN*CC;
        W   = klin_w + (size_t)dt*CC*CC + nbase;
        bias = klin_b + dt*CC;
        int slot = (et >= 2) ? 1 : 0;
        colsum = d_COLSUM + ((b*2 + dt)*2 + slot)*CC;
    }

    float acc[2][4][4];
    #pragma unroll
    for (int i = 0; i < 2; i++)
        #pragma unroll
        for (int j = 0; j < 4; j++)
            #pragma unroll
            for (int k = 0; k < 4; k++) acc[i][j][k] = 0.f;

    const int m0 = blockIdx.x * 128;
    const int ar  = tid >> 1;
    const int ak4 = (tid & 1) * 4;
    const int wk  = tid >> 4;             // 0..15 (only <8 used for W, tid<128)
    const int wn4 = (tid & 15) * 4;
    const int am  = m0 + ar;
    const bool aok = (am < NN);
    const bool wload = (tid < 128);

    // prologue: issue chunks 0..2
    #pragma unroll
    for (int p = 0; p < 3; p++){
        if (p < NCH){
            const float* Abase = A0; int koff = p*8;
            if (KTOT == 256 && koff >= 128){ Abase = A1; koff -= 128; }
            cpa16(&As[p][ar][ak4], Abase + (size_t)am*CC + koff + ak4, aok);
            if (wload) cpa16(&Ws[p][wk][wn4], W + (size_t)(p*8 + wk)*CC + wn4, true);
        }
        CPA_COMMIT();
    }
    CPA_WAIT2();
    __syncthreads();

    for (int kc = 0; kc < NCH; kc++){
        const int buf = kc & 3;

        unsigned afr[2][4], bfr[4][2];
        #pragma unroll
        for (int mt = 0; mt < 2; mt++){
            const float* pa = &As[buf][wm + mt*16 + r][c];
            afr[mt][0] = __float_as_uint(pa[0]);
            afr[mt][1] = __float_as_uint(pa[8*12]);
            afr[mt][2] = __float_as_uint(pa[4]);
            afr[mt][3] = __float_as_uint(pa[8*12 + 4]);
        }
        #pragma unroll
        for (int nt = 0; nt < 4; nt++){
            const float* pb = &Ws[buf][c][wnq + nt*8 + r];
            bfr[nt][0] = __float_as_uint(pb[0]);
            bfr[nt][1] = __float_as_uint(pb[4*72]);
        }
        #pragma unroll
        for (int mt = 0; mt < 2; mt++)
            #pragma unroll
            for (int nt = 0; nt < 4; nt++)
                mma_tf32(acc[mt][nt], afr[mt], bfr[nt]);

        {
            int kn = (kc + 3) * 8;
            if (kn < KTOT){
                const float* Abase = A0; int koff = kn;
                if (KTOT == 256 && koff >= 128){ Abase = A1; koff -= 128; }
                const int nb = (kc + 3) & 3;
                cpa16(&As[nb][ar][ak4], Abase + (size_t)am*CC + koff + ak4, aok);
                if (wload) cpa16(&Ws[nb][wk][wn4], W + (size_t)(kn + wk)*CC + wn4, true);
            }
            CPA_COMMIT();
        }
        CPA_WAIT2();
        __syncthreads();
    }

    // ---- epilogue (frag map: c0:(r,2c) c1:(r,2c+1) c2:(r+8,2c) c3:(r+8,2c+1))
    if (STAGE == 3){
        if (tid < 64) cs[tid] = 0.f;
        __syncthreads();
        #pragma unroll
        for (int nt = 0; nt < 4; nt++){
            int lcol = wnq + nt*8 + 2*c;
            float b0 = bias[nbase + lcol], b1 = bias[nbase + lcol + 1];
            float p0 = 0.f, p1 = 0.f;
            #pragma unroll
            for (int mt = 0; mt < 2; mt++){
                int row0 = m0 + wm + mt*16 + r;
                if (row0 < NN){
                    p0 += tanhf(acc[mt][nt][0] + b0);
                    p1 += tanhf(acc[mt][nt][1] + b1);
                }
                if (row0 + 8 < NN){
                    p0 += tanhf(acc[mt][nt][2] + b0);
                    p1 += tanhf(acc[mt][nt][3] + b1);
                }
            }
            atomicAdd(&cs[lcol], p0);
            atomicAdd(&cs[lcol + 1], p1);
        }
        __syncthreads();
        if (tid < 64) atomicAdd(&colsum[nbase + tid], cs[tid]);
    } else {
        #pragma unroll
        for (int mt = 0; mt < 2; mt++){
            int row0 = m0 + wm + mt*16 + r;
            #pragma unroll
            for (int nt = 0; nt < 4; nt++){
                int lcol = wnq + nt*8 + 2*c;
                float v0 = acc[mt][nt][0], v1 = acc[mt][nt][1];
                float v2 = acc[mt][nt][2], v3 = acc[mt][nt][3];
                if (STAGE == 2){
                    float b0 = bias[nbase + lcol], b1 = bias[nbase + lcol + 1];
                    v0 = tanhf(fmaxf(v0 + b0, 0.f));
                    v1 = tanhf(fmaxf(v1 + b1, 0.f));
                    v2 = tanhf(fmaxf(v2 + b0, 0.f));
                    v3 = tanhf(fmaxf(v3 + b1, 0.f));
                }
                if (row0 < NN)     *(float2*)&OUT[(size_t)row0*CC + nbase + lcol]     = make_float2(v0, v1);
                if (row0 + 8 < NN) *(float2*)&OUT[(size_t)(row0+8)*CC + nbase + lcol] = make_float2(v2, v3);
            }
        }
    }
}

// ---------------- per-destination-node softmax + weighted aggregation -------
// warp-per-node: 256-thr block = 8 nodes; lane owns 4 channels (float4)
__global__ void __launch_bounds__(256) node_aggregate(){
    const int etb  = blockIdx.y;
    const int warp = threadIdx.x >> 5;
    const int lane = threadIdx.x & 31;
    const int i    = blockIdx.x * 8 + warp;   // grid.x = 625, 625*8 = 5000
    const int et   = etb >> 1, b = etb & 1;
    const int st   = et_src(et);

    const int rbase = etb * (NN + 1);
    const int beg = d_ROWP[rbase + i];
    const int end = d_ROWP[rbase + i + 1];
    float* aggr = d_AGGR + ((size_t)etb*NN + i)*CC;
    const int c0 = lane * 4;
    if (end == beg){ *(float4*)(aggr + c0) = make_float4(0.f,0.f,0.f,0.f); return; }

    const float* al = d_EALPHA + (size_t)etb*EE;

    float m = -1e30f;
    for (int e = beg + lane; e < end; e += 32) m = fmaxf(m, al[e]);
    m = warpMax(m);
    float s = 0.f;
    for (int e = beg + lane; e < end; e += 32) s += expf(al[e] - m);
    s = warpSum(s);
    const float inv = 1.f / s;

    const float4 uc4  = *(const float4*)(d_U + et*CC + c0);
    const float4 vc4  = *(const float4*)(d_V + et*CC + c0);
    const float4 y2c4 = *(const float4*)(d_Y2 + ((size_t)etb*NN + i)*CC + c0);
    const float* xs  = d_XN + (size_t)(b*2 + st)*NN*CC;
    const float* y1  = d_Y1 + (size_t)etb*NN*CC;
    const int*   es  = d_ESRC + (size_t)etb*EE;
    const float* ewv = d_EWS  + (size_t)etb*EE;

    float4 acc = make_float4(0.f, 0.f, 0.f, 0.f);
    int e = beg;
    for (; e + 2 <= end; e += 2){
        int   s0 = es[e],     s1 = es[e+1];
        float w0 = expf(al[e]   - m) * inv;
        float w1 = expf(al[e+1] - m) * inv;
        float q0 = ewv[e], q1 = ewv[e+1];
        float4 ya = *(const float4*)(y1 + (size_t)s0*CC + c0);
        float4 xa = *(const float4*)(xs + (size_t)s0*CC + c0);
        float4 yb = *(const float4*)(y1 + (size_t)s1*CC + c0);
        float4 xb = *(const float4*)(xs + (size_t)s1*CC + c0);
        acc.x = fmaf(w0 * xa.x, ya.x + y2c4.x + fmaf(q0, uc4.x, vc4.x), acc.x);
        acc.y = fmaf(w0 * xa.y, ya.y + y2c4.y + fmaf(q0, uc4.y, vc4.y), acc.y);
        acc.z = fmaf(w0 * xa.z, ya.z + y2c4.z + fmaf(q0, uc4.z, vc4.z), acc.z);
        acc.w = fmaf(w0 * xa.w, ya.w + y2c4.w + fmaf(q0, uc4.w, vc4.w), acc.w);
        acc.x = fmaf(w1 * xb.x, yb.x + y2c4.x + fmaf(q1, uc4.x, vc4.x), acc.x);
        acc.y = fmaf(w1 * xb.y, yb.y + y2c4.y + fmaf(q1, uc4.y, vc4.y), acc.y);
        acc.z = fmaf(w1 * xb.z, yb.z + y2c4.z + fmaf(q1, uc4.z, vc4.z), acc.z);
        acc.w = fmaf(w1 * xb.w, yb.w + y2c4.w + fmaf(q1, uc4.w, vc4.w), acc.w);
    }
    if (e < end){
        int   s0 = es[e];
        float w0 = expf(al[e] - m) * inv;
        float q0 = ewv[e];
        float4 ya = *(const float4*)(y1 + (size_t)s0*CC + c0);
        float4 xa = *(const float4*)(xs + (size_t)s0*CC + c0);
        acc.x = fmaf(w0 * xa.x, ya.x + y2c4.x + fmaf(q0, uc4.x, vc4.x), acc.x);
        acc.y = fmaf(w0 * xa.y, ya.y + y2c4.y + fmaf(q0, uc4.y, vc4.y), acc.y);
        acc.z = fmaf(w0 * xa.z, ya.z + y2c4.z + fmaf(q0, uc4.z, vc4.z), acc.z);
        acc.w = fmaf(w0 * xa.w, ya.w + y2c4.w + fmaf(q0, uc4.w, vc4.w), acc.w);
    }
    *(float4*)(aggr + c0) = acc;
}

// ---------------- semantic attention finalize -------------------------------
__global__ void score_kernel(const float* __restrict__ q){
    int z = blockIdx.x;
    int nt = z & 1;
    int tid = threadIdx.x;
    __shared__ float red[8];
    const float* cs = d_COLSUM + z*2*CC;
    float qv = q[nt*CC + tid];
    float p0 = qv * cs[tid];
    float p1 = qv * cs[CC + tid];
    p0 = warpSum(p0); p1 = warpSum(p1);
    if ((tid & 31) == 0){ red[tid >> 5] = p0; red[4 + (tid >> 5)] = p1; }
    __syncthreads();
    if (tid == 0){
        float s0 = (red[0] + red[1] + red[2] + red[3]) / (float)NN;
        float s1 = (red[4] + red[5] + red[6] + red[7]) / (float)NN;
        float mx = fmaxf(s0, s1);
        float e0 = expf(s0 - mx), e1 = expf(s1 - mx);
        float invd = 1.f / (e0 + e1);
        d_ATTN[z*2 + 0] = e0 * invd;
        d_ATTN[z*2 + 1] = e1 * invd;
    }
}

__global__ void combine_kernel(float* __restrict__ out){
    int idx = blockIdx.x * 256 + threadIdx.x;
    if (idx >= BB*2*NN*CC) return;
    int c   = idx % CC;
    int row = (idx / CC) % (2*NN);
    int b   = idx / (2*NN*CC);
    int nt  = (row >= NN) ? 1 : 0;
    int n   = row - nt*NN;
    int etA = nt;
    int etB = 3 - nt;
    float a0 = d_ATTN[(b*2 + nt)*2 + 0];
    float a1 = d_ATTN[(b*2 + nt)*2 + 1];
    float o0 = d_OUTE[(((size_t)etA*BB + b)*NN + n)*CC + c];
    float o1 = d_OUTE[(((size_t)etB*BB + b)*NN + n)*CC + c];
    out[idx] = fmaf(a0, o0, a1 * o1);
}

// ---------------- launch -----------------------------------------------------
extern "C" void kernel_launch(void* const* d_in, const int* in_sizes, int n_in,
                              void* d_out, int out_size)
{
    const float* x       = (const float*)d_in[0];
    const int*   eidx    = (const int*)  d_in[1];
    const float* ew      = (const float*)d_in[2];
    const float* proj_w  = (const float*)d_in[3];
    const float* proj_b  = (const float*)d_in[4];
    const float* q       = (const float*)d_in[5];
    const float* klin_w  = (const float*)d_in[6];
    const float* klin_b  = (const float*)d_in[7];
    const float* lin_src = (const float*)d_in[8];
    const float* lin_dst = (const float*)d_in[9];
    const float* eproj_w = (const float*)d_in[10];
    const float* eproj_b = (const float*)d_in[11];
    const float* agg_w   = (const float*)d_in[12];
    const float* agg_b   = (const float*)d_in[13];
    const float* att_w   = (const float*)d_in[14];
    const float* att_b   = (const float*)d_in[15];
    float* out = (float*)d_out;

    zero_kernel<<<(ETB*NN + 255)/256, 256>>>();
    uv_kernel<<<TT, CC>>>(eproj_w, eproj_b, att_w, att_b);

    const int MB = (NN + 127) / 128;   // 40
    dim3 g0(MB, 4);
    gemm_stage0<<<g0, 256>>>(x, proj_w, proj_b);
    dim3 g1(MB, 32);                   // 16 z-slices x 2 n-halves
    gemm_mma<1><<<g1, 256>>>(att_w, agg_w, agg_b, klin_w, klin_b);

    asrc_kernel<<<(ETB*NN + 7)/8, 256>>>(lin_src, lin_dst);
    hist_kernel<<<(ETB*EE)/256, 256>>>(eidx);
    scan_kernel<<<ETB, 1024>>>();
    scatter_kernel<<<(ETB*EE)/256, 256>>>(eidx, ew);

    dim3 ga(NN/8, ETB);   // 625 x 8, warp-per-node
    node_aggregate<<<ga, 256>>>();

    dim3 g2(MB, 16);                   // 8 etb x 2 n-halves
    gemm_mma<2><<<g2, 256>>>(att_w, agg_w, agg_b, klin_w, klin_b);
    dim3 g3(MB, 16);
    gemm_mma<3><<<g3, 256>>>(att_w, agg_w, agg_b, klin_w, klin_b);

    score_kernel<<<BB*2, 128>>>(q);
    combine_kernel<<<(BB*2*NN*CC + 255)/256, 256>>>(out);
}

// round 16
// speedup vs baseline: 1.0906x; 1.0906x over previous
#include <cuda_runtime.h>
#include <stdint.h>
#include <math.h>

#define BB 2
#define NN 5000
#define CC 128
#define EE 65536
#define TT 4
#define ETB (TT*BB)   /* 8 */

typedef unsigned long long ull;

// ---------------- scratch (static device globals; no allocation) ------------
__device__ float d_XN[BB*2*NN*CC];
__device__ float d_Y1[ETB*NN*CC];
__device__ float d_Y2[ETB*NN*CC];
__device__ float d_AGGR[ETB*NN*CC];
__device__ float d_OUTE[ETB*NN*CC];
__device__ float d_ASRC[ETB*NN];
__device__ float d_ADST[ETB*NN];
__device__ float d_U[TT*CC];
__device__ float d_V[TT*CC];
__device__ int   d_CNT[ETB*NN];
__device__ int   d_FILL[ETB*NN];
__device__ int   d_ROWP[ETB*(NN+1)];
__device__ int   d_ESRC[ETB*EE];
__device__ float d_EWS[ETB*EE];
__device__ float d_COLSUM[BB*2*2*CC];
__device__ float d_ATTN[BB*2*2];

__device__ __forceinline__ int et_src(int et){ return et & 1; }
__device__ __forceinline__ int et_dst(int et){ return (et & 1) ^ (et >> 1); }

__device__ __forceinline__ float warpMax(float v){
    #pragma unroll
    for (int o = 16; o > 0; o >>= 1) v = fmaxf(v, __shfl_xor_sync(0xffffffffu, v, o));
    return v;
}
__device__ __forceinline__ float warpSum(float v){
    #pragma unroll
    for (int o = 16; o > 0; o >>= 1) v += __shfl_xor_sync(0xffffffffu, v, o);
    return v;
}

// ---- packed fp32x2 helpers (Blackwell FFMA2) — stage 0 only -----------------
__device__ __forceinline__ ull pack2(float x, float y){
    ull r; asm("mov.b64 %0, {%1, %2};" : "=l"(r) : "f"(x), "f"(y)); return r;
}
__device__ __forceinline__ ull dup2(float x){
    ull r; asm("mov.b64 %0, {%1, %1};" : "=l"(r) : "f"(x)); return r;
}
__device__ __forceinline__ void fma2(ull &d, ull a, ull b){
    asm("fma.rn.f32x2 %0, %1, %2, %0;" : "+l"(d) : "l"(a), "l"(b));
}
__device__ __forceinline__ float2 unpack2(ull v){
    float2 r; asm("mov.b64 {%0, %1}, %2;" : "=f"(r.x), "=f"(r.y) : "l"(v)); return r;
}

// ---- tf32 warp MMA ----------------------------------------------------------
__device__ __forceinline__ void mma_tf32(float* d, const unsigned* a, const unsigned* b){
    asm volatile(
        "mma.sync.aligned.m16n8k8.row.col.f32.tf32.tf32.f32 "
        "{%0,%1,%2,%3}, {%4,%5,%6,%7}, {%8,%9}, {%0,%1,%2,%3};"
        : "+f"(d[0]), "+f"(d[1]), "+f"(d[2]), "+f"(d[3])
        : "r"(a[0]), "r"(a[1]), "r"(a[2]), "r"(a[3]), "r"(b[0]), "r"(b[1]));
}

// ---- cp.async helpers -------------------------------------------------------
__device__ __forceinline__ void cpa16(void* sdst, const void* gsrc, bool ok){
    unsigned int sa = (unsigned int)__cvta_generic_to_shared(sdst);
    int sz = ok ? 16 : 0;
    asm volatile("cp.async.cg.shared.global [%0], [%1], 16, %2;" :: "r"(sa), "l"(gsrc), "r"(sz));
}
#define CPA_COMMIT() asm volatile("cp.async.commit_group;")
#define CPA_WAIT2()  asm volatile("cp.async.wait_group 2;" ::: "memory")

// ---------------- misc small kernels ----------------------------------------
__global__ void zero_kernel(){
    int i = blockIdx.x * blockDim.x + threadIdx.x;
    if (i < ETB*NN){ d_CNT[i] = 0; d_FILL[i] = 0; }
    if (i < BB*2*2*CC) d_COLSUM[i] = 0.f;
}

__global__ void uv_kernel(const float* __restrict__ eproj_w, const float* __restrict__ eproj_b,
                          const float* __restrict__ att_w,   const float* __restrict__ att_b){
    int et = blockIdx.x;
    int cp = threadIdx.x;
    const float* W3 = att_w + (size_t)et*3*CC*CC + 2*CC*CC;
    float u = 0.f, v = 0.f;
    #pragma unroll 4
    for (int c = 0; c < CC; c++){
        float wv = W3[c*CC + cp];
        u = fmaf(eproj_w[et*CC + c], wv, u);
        v = fmaf(eproj_b[et*CC + c], wv, v);
    }
    v += att_b[et*CC + cp];
    d_U[et*CC + cp] = u;
    d_V[et*CC + cp] = v;
}

__global__ void asrc_kernel(const float* __restrict__ lin_src, const float* __restrict__ lin_dst){
    int g = blockIdx.x * 8 + (threadIdx.x >> 5);
    int lane = threadIdx.x & 31;
    if (g >= ETB*NN) return;
    int etb = g / NN, n = g % NN;
    int et = etb >> 1, b = etb & 1;
    int st = et_src(et), dt = et_dst(et);
    const float* xs = d_XN + ((size_t)(b*2 + st)*NN + n)*CC;
    const float* xd = d_XN + ((size_t)(b*2 + dt)*NN + n)*CC;
    float s1 = 0.f, s2 = 0.f;
    #pragma unroll
    for (int c = lane; c < CC; c += 32){
        s1 = fmaf(xs[c], lin_src[et*CC + c], s1);
        s2 = fmaf(xd[c], lin_dst[et*CC + c], s2);
    }
    s1 = warpSum(s1); s2 = warpSum(s2);
    if (lane == 0){
        d_ASRC[etb*NN + n] = s1;
        d_ADST[etb*NN + n] = s2;
    }
}

__global__ void hist_kernel(const int* __restrict__ eidx){
    int idx = blockIdx.x * 256 + threadIdx.x;
    int etb = idx >> 16;
    int e   = idx & (EE - 1);
    int dst = eidx[(etb*2 + 1)*EE + e];
    atomicAdd(&d_CNT[etb*NN + dst], 1);
}

__global__ void scan_kernel(){
    int etb = blockIdx.x;
    int tid = threadIdx.x;                      // 1024 threads
    __shared__ int sh[1024];
    int base = etb * NN;
    int vals[5];
    int tot = 0;
    int start = tid * 5;
    #pragma unroll
    for (int k = 0; k < 5; k++){
        int idx = start + k;
        int c = (idx < NN) ? d_CNT[base + idx] : 0;
        vals[k] = tot;
        tot += c;
    }
    sh[tid] = tot;
    __syncthreads();
    for (int off = 1; off < 1024; off <<= 1){
        int v = (tid >= off) ? sh[tid - off] : 0;
        __syncthreads();
        sh[tid] += v;
        __syncthreads();
    }
    int offset = sh[tid] - tot;
    int rbase = etb * (NN + 1);
    #pragma unroll
    for (int k = 0; k < 5; k++){
        int idx = start + k;
        if (idx < NN) d_ROWP[rbase + idx] = offset + vals[k];
    }
    if (tid == 0) d_ROWP[rbase + NN] = EE;
}

// positions only — NO alpha (keeps this chain independent of the GEMM chain)
__global__ void scatter_kernel(const int* __restrict__ eidx, const float* __restrict__ ew){
    int idx = blockIdx.x * 256 + threadIdx.x;
    int etb = idx >> 16;
    int e   = idx & (EE - 1);
    int src = eidx[(etb*2 + 0)*EE + e];
    int dst = eidx[(etb*2 + 1)*EE + e];
    int pos = d_ROWP[etb*(NN+1) + dst] + atomicAdd(&d_FILL[etb*NN + dst], 1);
    int o = etb*EE + pos;
    d_ESRC[o] = src;
    d_EWS[o]  = ew[etb*EE + e];
}

// ---------------- STAGE 0 GEMM (fp32 FFMA2, exact — feeds softmax logits) ----
__global__ void __launch_bounds__(256)
gemm_stage0(const float* __restrict__ x,
            const float* __restrict__ proj_w, const float* __restrict__ proj_b)
{
    __shared__ __align__(16) float As[2][8][132];
    __shared__ __align__(16) float Ws[2][8][128];

    const int z   = blockIdx.y;
    const int tid = threadIdx.x;
    const int tx  = tid & 15;
    const int ty  = tid >> 4;

    int b = z >> 1, nt = z & 1;
    const float* A0  = x + (size_t)(b*2*NN + nt*NN)*CC;
    const float* W   = proj_w + (size_t)nt*CC*CC;
    const float* bias = proj_b + nt*CC;
    float* OUT = d_XN + (size_t)z*NN*CC;

    ull acc[8][4];
    #pragma unroll
    for (int i = 0; i < 8; i++)
        #pragma unroll
        for (int j = 0; j < 4; j++) acc[i][j] = 0ull;

    const int m0 = blockIdx.x * 128;
    const int ar  = tid >> 1;
    const int ak4 = (tid & 1) * 4;
    const int wk  = tid >> 5;
    const int wn  = (tid & 31) * 4;
    const int am  = m0 + ar;
    const bool aok = (am < NN);

    float4 aReg = make_float4(0.f,0.f,0.f,0.f);
    if (aok) aReg = *(const float4*)(A0 + (size_t)am*CC + ak4);
    float4 wReg = *(const float4*)(W + (size_t)wk*CC + wn);

    As[0][ak4+0][ar] = aReg.x;
    As[0][ak4+1][ar] = aReg.y;
    As[0][ak4+2][ar] = aReg.z;
    As[0][ak4+3][ar] = aReg.w;
    *(float4*)&Ws[0][wk][wn] = wReg;
    __syncthreads();

    for (int kc = 0; kc < 128; kc += 8){
        const int buf = (kc >> 3) & 1;
        const int kn  = kc + 8;
        const bool more = (kn < 128);

        if (more){
            aReg = make_float4(0.f,0.f,0.f,0.f);
            if (aok) aReg = *(const float4*)(A0 + (size_t)am*CC + kn + ak4);
            wReg = *(const float4*)(W + (size_t)(kn + wk)*CC + wn);
        }

        #pragma unroll
        for (int kk = 0; kk < 8; kk++){
            float4 bl = *(float4*)&Ws[buf][kk][tx*4];
            float4 bh = *(float4*)&Ws[buf][kk][64 + tx*4];
            ull bp0 = pack2(bl.x, bl.y);
            ull bp1 = pack2(bl.z, bl.w);
            ull bp2 = pack2(bh.x, bh.y);
            ull bp3 = pack2(bh.z, bh.w);
            float4 a0 = *(float4*)&As[buf][kk][ty*8];
            float4 a1 = *(float4*)&As[buf][kk][ty*8 + 4];
            float av[8] = {a0.x, a0.y, a0.z, a0.w, a1.x, a1.y, a1.z, a1.w};
            #pragma unroll
            for (int i = 0; i < 8; i++){
                ull ad = dup2(av[i]);
                fma2(acc[i][0], ad, bp0);
                fma2(acc[i][1], ad, bp1);
                fma2(acc[i][2], ad, bp2);
                fma2(acc[i][3], ad, bp3);
            }
        }

        if (more){
            const int nb = buf ^ 1;
            As[nb][ak4+0][ar] = aReg.x;
            As[nb][ak4+1][ar] = aReg.y;
            As[nb][ak4+2][ar] = aReg.z;
            As[nb][ak4+3][ar] = aReg.w;
            *(float4*)&Ws[nb][wk][wn] = wReg;
        }
        __syncthreads();
    }

    const int c0 = tx*4;
    const int c1 = 64 + tx*4;
    #pragma unroll
    for (int i = 0; i < 8; i++){
        int m = m0 + ty*8 + i;
        if (m < NN){
            float2 v0 = unpack2(acc[i][0]);
            float2 v1 = unpack2(acc[i][1]);
            float2 v2 = unpack2(acc[i][2]);
            float2 v3 = unpack2(acc[i][3]);
            v0.x += bias[c0];   v0.y += bias[c0+1];
            v1.x += bias[c0+2]; v1.y += bias[c0+3];
            v2.x += bias[c1];   v2.y += bias[c1+1];
            v3.x += bias[c1+2]; v3.y += bias[c1+3];
            float* dst = OUT + (size_t)m*CC;
            *(float4*)(dst + c0) = make_float4(v0.x, v0.y, v1.x, v1.y);
            *(float4*)(dst + c1) = make_float4(v2.x, v2.y, v3.x, v3.y);
        }
    }
}

// ---------------- STAGES 1/2/3 GEMM: tf32 mma.sync, 4-stage cp.async ---------
template<int STAGE>
__global__ void __launch_bounds__(256, 3)
gemm_mma(const float* __restrict__ att_w,
         const float* __restrict__ agg_w,  const float* __restrict__ agg_b,
         const float* __restrict__ klin_w, const float* __restrict__ klin_b)
{
    constexpr int KTOT = (STAGE == 2) ? 256 : 128;
    constexpr int NCH  = KTOT / 8;
    __shared__ __align__(16) float As[4][128][12];
    __shared__ __align__(16) float Ws[4][8][72];
    __shared__ float cs[64];

    const int z2   = blockIdx.y;
    const int nbase = (z2 & 1) * 64;
    const int z    = z2 >> 1;
    const int tid  = threadIdx.x;
    const int wid  = tid >> 5;
    const int lane = tid & 31;
    const int wm   = (wid & 3) * 32;
    const int wnq  = (wid >> 2) * 32;
    const int r    = lane >> 2;
    const int c    = lane & 3;

    const float* A0 = nullptr; const float* A1 = nullptr;
    const float* W  = nullptr; const float* bias = nullptr;
    float* OUT = nullptr; float* colsum = nullptr;

    if (STAGE == 1){
        int etb = z >> 1, which = z & 1;
        int et = etb >> 1, b = etb & 1;
        int nt = which ? et_dst(et) : et_src(et);
        A0  = d_XN + (size_t)(b*2 + nt)*NN*CC;
        W   = att_w + (size_t)et*3*CC*CC + (size_t)which*CC*CC + nbase;
        OUT = (which ? d_Y2 : d_Y1) + (size_t)etb*NN*CC;
    } else if (STAGE == 2){
        int etb = z; int et = etb >> 1, b = etb & 1;
        int dt = et_dst(et);
        A0  = d_AGGR + (size_t)etb*NN*CC;
        A1  = d_XN + (size_t)(b*2 + dt)*NN*CC;
        W   = agg_w + (size_t)et*2*CC*CC + nbase;
        bias = agg_b + et*CC;
        OUT = d_OUTE + (size_t)etb*NN*CC;
    } else {
        int etb = z; int et = etb >> 1, b = etb & 1;
        int dt = et_dst(et);
        A0  = d_OUTE + (size_t)etb*NN*CC;
        W   = klin_w + (size_t)dt*CC*CC + nbase;
        bias = klin_b + dt*CC;
        int slot = (et >= 2) ? 1 : 0;
        colsum = d_COLSUM + ((b*2 + dt)*2 + slot)*CC;
    }

    float acc[2][4][4];
    #pragma unroll
    for (int i = 0; i < 2; i++)
        #pragma unroll
        for (int j = 0; j < 4; j++)
            #pragma unroll
            for (int k = 0; k < 4; k++) acc[i][j][k] = 0.f;

    const int m0 = blockIdx.x * 128;
    const int ar  = tid >> 1;
    const int ak4 = (tid & 1) * 4;
    const int wk  = tid >> 4;
    const int wn4 = (tid & 15) * 4;
    const int am  = m0 + ar;
    const bool aok = (am < NN);
    const bool wload = (tid < 128);

    #pragma unroll
    for (int p = 0; p < 3; p++){
        if (p < NCH){
            const float* Abase = A0; int koff = p*8;
            if (KTOT == 256 && koff >= 128){ Abase = A1; koff -= 128; }
            cpa16(&As[p][ar][ak4], Abase + (size_t)am*CC + koff + ak4, aok);
            if (wload) cpa16(&Ws[p][wk][wn4], W + (size_t)(p*8 + wk)*CC + wn4, true);
        }
        CPA_COMMIT();
    }
    CPA_WAIT2();
    __syncthreads();

    for (int kc = 0; kc < NCH; kc++){
        const int buf = kc & 3;

        unsigned afr[2][4], bfr[4][2];
        #pragma unroll
        for (int mt = 0; mt < 2; mt++){
            const float* pa = &As[buf][wm + mt*16 + r][c];
            afr[mt][0] = __float_as_uint(pa[0]);
            afr[mt][1] = __float_as_uint(pa[8*12]);
            afr[mt][2] = __float_as_uint(pa[4]);
            afr[mt][3] = __float_as_uint(pa[8*12 + 4]);
        }
        #pragma unroll
        for (int nt = 0; nt < 4; nt++){
            const float* pb = &Ws[buf][c][wnq + nt*8 + r];
            bfr[nt][0] = __float_as_uint(pb[0]);
            bfr[nt][1] = __float_as_uint(pb[4*72]);
        }
        #pragma unroll
        for (int mt = 0; mt < 2; mt++)
            #pragma unroll
            for (int nt = 0; nt < 4; nt++)
                mma_tf32(acc[mt][nt], afr[mt], bfr[nt]);

        {
            int kn = (kc + 3) * 8;
            if (kn < KTOT){
                const float* Abase = A0; int koff = kn;
                if (KTOT == 256 && koff >= 128){ Abase = A1; koff -= 128; }
                const int nb = (kc + 3) & 3;
                cpa16(&As[nb][ar][ak4], Abase + (size_t)am*CC + koff + ak4, aok);
                if (wload) cpa16(&Ws[nb][wk][wn4], W + (size_t)(kn + wk)*CC + wn4, true);
            }
            CPA_COMMIT();
        }
        CPA_WAIT2();
        __syncthreads();
    }

    if (STAGE == 3){
        if (tid < 64) cs[tid] = 0.f;
        __syncthreads();
        #pragma unroll
        for (int nt = 0; nt < 4; nt++){
            int lcol = wnq + nt*8 + 2*c;
            float b0 = bias[nbase + lcol], b1 = bias[nbase + lcol + 1];
            float p0 = 0.f, p1 = 0.f;
            #pragma unroll
            for (int mt = 0; mt < 2; mt++){
                int row0 = m0 + wm + mt*16 + r;
                if (row0 < NN){
                    p0 += tanhf(acc[mt][nt][0] + b0);
                    p1 += tanhf(acc[mt][nt][1] + b1);
                }
                if (row0 + 8 < NN){
                    p0 += tanhf(acc[mt][nt][2] + b0);
                    p1 += tanhf(acc[mt][nt][3] + b1);
                }
            }
            atomicAdd(&cs[lcol], p0);
            atomicAdd(&cs[lcol + 1], p1);
        }
        __syncthreads();
        if (tid < 64) atomicAdd(&colsum[nbase + tid], cs[tid]);
    } else {
        #pragma unroll
        for (int mt = 0; mt < 2; mt++){
            int row0 = m0 + wm + mt*16 + r;
            #pragma unroll
            for (int nt = 0; nt < 4; nt++){
                int lcol = wnq + nt*8 + 2*c;
                float v0 = acc[mt][nt][0], v1 = acc[mt][nt][1];
                float v2 = acc[mt][nt][2], v3 = acc[mt][nt][3];
                if (STAGE == 2){
                    float b0 = bias[nbase + lcol], b1 = bias[nbase + lcol + 1];
                    v0 = tanhf(fmaxf(v0 + b0, 0.f));
                    v1 = tanhf(fmaxf(v1 + b1, 0.f));
                    v2 = tanhf(fmaxf(v2 + b0, 0.f));
                    v3 = tanhf(fmaxf(v3 + b1, 0.f));
                }
                if (row0 < NN)     *(float2*)&OUT[(size_t)row0*CC + nbase + lcol]     = make_float2(v0, v1);
                if (row0 + 8 < NN) *(float2*)&OUT[(size_t)(row0+8)*CC + nbase + lcol] = make_float2(v2, v3);
            }
        }
    }
}

// ---------------- per-destination-node softmax + weighted aggregation -------
// warp-per-node; alpha computed inline from ASRC/ADST (no EALPHA array)
__global__ void __launch_bounds__(256) node_aggregate(){
    const int etb  = blockIdx.y;
    const int warp = threadIdx.x >> 5;
    const int lane = threadIdx.x & 31;
    const int i    = blockIdx.x * 8 + warp;   // grid.x = 625
    const int et   = etb >> 1, b = etb & 1;
    const int st   = et_src(et);

    const int rbase = etb * (NN + 1);
    const int beg = d_ROWP[rbase + i];
    const int end = d_ROWP[rbase + i + 1];
    float* aggr = d_AGGR + ((size_t)etb*NN + i)*CC;
    const int c0 = lane * 4;
    if (end == beg){ *(float4*)(aggr + c0) = make_float4(0.f,0.f,0.f,0.f); return; }

    const float* asrc = d_ASRC + etb*NN;
    const float  adst = d_ADST[etb*NN + i];
    const int*   es   = d_ESRC + (size_t)etb*EE;
    const float* ewv  = d_EWS  + (size_t)etb*EE;

    // pass 1: segment max of leaky(asrc[s]+adst)
    float m = -1e30f;
    for (int e = beg + lane; e < end; e += 32){
        float a = asrc[es[e]] + adst;
        a = (a > 0.f) ? a : 0.2f * a;
        m = fmaxf(m, a);
    }
    m = warpMax(m);
    // pass 2: denom
    float s = 0.f;
    for (int e = beg + lane; e < end; e += 32){
        float a = asrc[es[e]] + adst;
        a = (a > 0.f) ? a : 0.2f * a;
        s += expf(a - m);
    }
    s = warpSum(s);
    const float inv = 1.f / s;

    const float4 uc4  = *(const float4*)(d_U + et*CC + c0);
    const float4 vc4  = *(const float4*)(d_V + et*CC + c0);
    const float4 y2c4 = *(const float4*)(d_Y2 + ((size_t)etb*NN + i)*CC + c0);
    const float* xs  = d_XN + (size_t)(b*2 + st)*NN*CC;
    const float* y1  = d_Y1 + (size_t)etb*NN*CC;

    float4 acc = make_float4(0.f, 0.f, 0.f, 0.f);
    int e = beg;
    for (; e + 2 <= end; e += 2){
        int   s0 = es[e],     s1 = es[e+1];
        float a0 = asrc[s0] + adst; a0 = (a0 > 0.f) ? a0 : 0.2f * a0;
        float a1 = asrc[s1] + adst; a1 = (a1 > 0.f) ? a1 : 0.2f * a1;
        float w0 = expf(a0 - m) * inv;
        float w1 = expf(a1 - m) * inv;
        float q0 = ewv[e], q1 = ewv[e+1];
        float4 ya = *(const float4*)(y1 + (size_t)s0*CC + c0);
        float4 xa = *(const float4*)(xs + (size_t)s0*CC + c0);
        float4 yb = *(const float4*)(y1 + (size_t)s1*CC + c0);
        float4 xb = *(const float4*)(xs + (size_t)s1*CC + c0);
        acc.x = fmaf(w0 * xa.x, ya.x + y2c4.x + fmaf(q0, uc4.x, vc4.x), acc.x);
        acc.y = fmaf(w0 * xa.y, ya.y + y2c4.y + fmaf(q0, uc4.y, vc4.y), acc.y);
        acc.z = fmaf(w0 * xa.z, ya.z + y2c4.z + fmaf(q0, uc4.z, vc4.z), acc.z);
        acc.w = fmaf(w0 * xa.w, ya.w + y2c4.w + fmaf(q0, uc4.w, vc4.w), acc.w);
        acc.x = fmaf(w1 * xb.x, yb.x + y2c4.x + fmaf(q1, uc4.x, vc4.x), acc.x);
        acc.y = fmaf(w1 * xb.y, yb.y + y2c4.y + fmaf(q1, uc4.y, vc4.y), acc.y);
        acc.z = fmaf(w1 * xb.z, yb.z + y2c4.z + fmaf(q1, uc4.z, vc4.z), acc.z);
        acc.w = fmaf(w1 * xb.w, yb.w + y2c4.w + fmaf(q1, uc4.w, vc4.w), acc.w);
    }
    if (e < end){
        int   s0 = es[e];
        float a0 = asrc[s0] + adst; a0 = (a0 > 0.f) ? a0 : 0.2f * a0;
        float w0 = expf(a0 - m) * inv;
        float q0 = ewv[e];
        float4 ya = *(const float4*)(y1 + (size_t)s0*CC + c0);
        float4 xa = *(const float4*)(xs + (size_t)s0*CC + c0);
        acc.x = fmaf(w0 * xa.x, ya.x + y2c4.x + fmaf(q0, uc4.x, vc4.x), acc.x);
        acc.y = fmaf(w0 * xa.y, ya.y + y2c4.y + fmaf(q0, uc4.y, vc4.y), acc.y);
        acc.z = fmaf(w0 * xa.z, ya.z + y2c4.z + fmaf(q0, uc4.z, vc4.z), acc.z);
        acc.w = fmaf(w0 * xa.w, ya.w + y2c4.w + fmaf(q0, uc4.w, vc4.w), acc.w);
    }
    *(float4*)(aggr + c0) = acc;
}

// ---------------- semantic attention finalize -------------------------------
__global__ void score_kernel(const float* __restrict__ q){
    int z = blockIdx.x;
    int nt = z & 1;
    int tid = threadIdx.x;
    __shared__ float red[8];
    const float* cs = d_COLSUM + z*2*CC;
    float qv = q[nt*CC + tid];
    float p0 = qv * cs[tid];
    float p1 = qv * cs[CC + tid];
    p0 = warpSum(p0); p1 = warpSum(p1);
    if ((tid & 31) == 0){ red[tid >> 5] = p0; red[4 + (tid >> 5)] = p1; }
    __syncthreads();
    if (tid == 0){
        float s0 = (red[0] + red[1] + red[2] + red[3]) / (float)NN;
        float s1 = (red[4] + red[5] + red[6] + red[7]) / (float)NN;
        float mx = fmaxf(s0, s1);
        float e0 = expf(s0 - mx), e1 = expf(s1 - mx);
        float invd = 1.f / (e0 + e1);
        d_ATTN[z*2 + 0] = e0 * invd;
        d_ATTN[z*2 + 1] = e1 * invd;
    }
}

__global__ void combine_kernel(float* __restrict__ out){
    int idx = blockIdx.x * 256 + threadIdx.x;
    if (idx >= BB*2*NN*CC) return;
    int c   = idx % CC;
    int row = (idx / CC) % (2*NN);
    int b   = idx / (2*NN*CC);
    int nt  = (row >= NN) ? 1 : 0;
    int n   = row - nt*NN;
    int etA = nt;
    int etB = 3 - nt;
    float a0 = d_ATTN[(b*2 + nt)*2 + 0];
    float a1 = d_ATTN[(b*2 + nt)*2 + 1];
    float o0 = d_OUTE[(((size_t)etA*BB + b)*NN + n)*CC + c];
    float o1 = d_OUTE[(((size_t)etB*BB + b)*NN + n)*CC + c];
    out[idx] = fmaf(a0, o0, a1 * o1);
}

// ---------------- launch (two capture streams, event fork/join) --------------
extern "C" void kernel_launch(void* const* d_in, const int* in_sizes, int n_in,
                              void* d_out, int out_size)
{
    const float* x       = (const float*)d_in[0];
    const int*   eidx    = (const int*)  d_in[1];
    const float* ew      = (const float*)d_in[2];
    const float* proj_w  = (const float*)d_in[3];
    const float* proj_b  = (const float*)d_in[4];
    const float* q       = (const float*)d_in[5];
    const float* klin_w  = (const float*)d_in[6];
    const float* klin_b  = (const float*)d_in[7];
    const float* lin_src = (const float*)d_in[8];
    const float* lin_dst = (const float*)d_in[9];
    const float* eproj_w = (const float*)d_in[10];
    const float* eproj_b = (const float*)d_in[11];
    const float* agg_w   = (const float*)d_in[12];
    const float* agg_b   = (const float*)d_in[13];
    const float* att_w   = (const float*)d_in[14];
    const float* att_b   = (const float*)d_in[15];
    float* out = (float*)d_out;

    static cudaStream_t sB = nullptr;
    static cudaEvent_t  eZ = nullptr, eB = nullptr;
    if (!sB){
        cudaStreamCreateWithFlags(&sB, cudaStreamNonBlocking);
        cudaEventCreateWithFlags(&eZ, cudaEventDisableTiming);
        cudaEventCreateWithFlags(&eB, cudaEventDisableTiming);
    }

    // fork point: zero (CNT/FILL/COLSUM)
    zero_kernel<<<(ETB*NN + 255)/256, 256>>>();
    cudaEventRecord(eZ, 0);
    cudaStreamWaitEvent(sB, eZ, 0);

    // stream B: CSR build (independent of GEMMs)
    hist_kernel<<<(ETB*EE)/256, 256, 0, sB>>>(eidx);
    scan_kernel<<<ETB, 1024, 0, sB>>>();
    scatter_kernel<<<(ETB*EE)/256, 256, 0, sB>>>(eidx, ew);
    cudaEventRecord(eB, sB);

    // stream 0: projection chain
    uv_kernel<<<TT, CC>>>(eproj_w, eproj_b, att_w, att_b);
    const int MB = (NN + 127) / 128;   // 40
    dim3 g0(MB, 4);
    gemm_stage0<<<g0, 256>>>(x, proj_w, proj_b);
    dim3 g1(MB, 32);
    gemm_mma<1><<<g1, 256>>>(att_w, agg_w, agg_b, klin_w, klin_b);
    asrc_kernel<<<(ETB*NN + 7)/8, 256>>>(lin_src, lin_dst);

    // join
    cudaStreamWaitEvent(0, eB, 0);

    dim3 ga(NN/8, ETB);
    node_aggregate<<<ga, 256>>>();

    dim3 g2(MB, 16);
    gemm_mma<2><<<g2, 256>>>(att_w, agg_w, agg_b, klin_w, klin_b);
    dim3 g3(MB, 16);
    gemm_mma<3><<<g3, 256>>>(att_w, agg_w, agg_b, klin_w, klin_b);

    score_kernel<<<BB*2, 128>>>(q);
    combine_kernel<<<(BB*2*NN*CC + 255)/256, 256>>>(out);
}